// round 7
// baseline (speedup 1.0000x reference)
#include <cuda_runtime.h>

#define NE 8
#define NF 32
#define EPSV 1e-5f
#define TPB 128

typedef unsigned long long u64;

__device__ __forceinline__ u64 bcast2(float v) {
    u64 r; asm("mov.b64 %0, {%1, %1};" : "=l"(r) : "f"(v)); return r;
}
__device__ __forceinline__ void up2(u64 v, float& a, float& b) {
    asm("mov.b64 {%0, %1}, %2;" : "=f"(a), "=f"(b) : "l"(v));
}
__device__ __forceinline__ u64 pack2(float a, float b) {
    u64 r; asm("mov.b64 %0, {%1, %2};" : "=l"(r) : "f"(a), "f"(b)); return r;
}
__device__ __forceinline__ u64 fma2(u64 a, u64 b, u64 c) {
    u64 d; asm("fma.rn.f32x2 %0, %1, %2, %3;" : "=l"(d) : "l"(a), "l"(b), "l"(c)); return d;
}
__device__ __forceinline__ u64 add2(u64 a, u64 b) {
    u64 d; asm("add.rn.f32x2 %0, %1, %2;" : "=l"(d) : "l"(a), "l"(b)); return d;
}
__device__ __forceinline__ u64 mul2(u64 a, u64 b) {
    u64 d; asm("mul.rn.f32x2 %0, %1, %2;" : "=l"(d) : "l"(a), "l"(b)); return d;
}
__device__ __forceinline__ float rsqrt_a(float v) {
    float r; asm("rsqrt.approx.f32 %0, %1;" : "=f"(r) : "f"(v)); return r;
}

// LayerNorm over 8 elements held as 4 packed f32x2.
__device__ __forceinline__ void ln8(const u64 r[4], const u64* gpk, const u64* bpk, u64 o[4]) {
    u64 s = add2(add2(r[0], r[1]), add2(r[2], r[3]));
    float a, b; up2(s, a, b);
    const float m = (a + b) * 0.125f;
    const u64 nm = bcast2(-m);
    u64 d0 = add2(r[0], nm), d1 = add2(r[1], nm), d2 = add2(r[2], nm), d3 = add2(r[3], nm);
    u64 v2 = mul2(d0, d0);
    v2 = fma2(d1, d1, v2); v2 = fma2(d2, d2, v2); v2 = fma2(d3, d3, v2);
    up2(v2, a, b);
    const float inv = rsqrt_a((a + b) * 0.125f + EPSV);
    const u64 i2 = bcast2(inv);
    o[0] = fma2(mul2(d0, i2), gpk[0], bpk[0]);
    o[1] = fma2(mul2(d1, i2), gpk[1], bpk[1]);
    o[2] = fma2(mul2(d2, i2), gpk[2], bpk[2]);
    o[3] = fma2(mul2(d3, i2), gpk[3], bpk[3]);
}

__global__ __launch_bounds__(TPB, 3) void tbq_kernel(
    const float* __restrict__ x,
    const float* __restrict__ Wq,  const float* __restrict__ bq,
    const float* __restrict__ theta_attn,
    const float* __restrict__ Wc,  const float* __restrict__ bc,
    const float* __restrict__ g1,  const float* __restrict__ beta1,
    const float* __restrict__ theta_ffn,
    const float* __restrict__ W1,  const float* __restrict__ b1,
    const float* __restrict__ W2,  const float* __restrict__ b2,
    const float* __restrict__ g2,  const float* __restrict__ beta2,
    float* __restrict__ out, int tokens)
{
    __shared__ __align__(16) float sWq[64];    // [k][j]
    __shared__ __align__(16) float sWc[64];    // [k][j]
    __shared__ __align__(16) float sW1[256];   // original [j][i], hidden contiguous
    __shared__ __align__(16) float sW2i[256];  // [p][j][half] = W2[2p+half][j]
    __shared__ __align__(16) float sbq[8], sbc[8], sth[8], sctf[8];
    __shared__ __align__(16) float sb1[32], sb2[8];
    __shared__ __align__(16) float sg1[8], sbe1[8], sg2[8], sbe2[8];
    __shared__ u64 sx1[16][TPB];               // x1 stash: [tok*4+j][lane], conflict-free

    const int t = threadIdx.x;
    if (t < 64) { sWq[t] = Wq[t]; sWc[t] = Wc[t]; }
    #pragma unroll
    for (int i = t; i < 256; i += TPB) {
        sW1[i] = W1[i];
        int p = i >> 4, r = i & 15, j = r >> 1, half = r & 1;
        sW2i[i] = W2[(2 * p + half) * NE + j];
    }
    if (t < 32) sb1[t] = b1[t];
    if (t < 8) {
        sbq[t] = bq[t];  sbc[t] = bc[t];
        sth[t] = theta_attn[t];
        sctf[t] = __cosf(theta_ffn[t]);
        sb2[t] = b2[t];
        sg1[t] = g1[t];  sbe1[t] = beta1[t];
        sg2[t] = g2[t];  sbe2[t] = beta2[t];
    }
    __syncthreads();

    const int base = (blockIdx.x * TPB + t) * 4;      // 4 tokens per thread
    if (base >= tokens) return;

    const u64* wq2  = reinterpret_cast<const u64*>(sWq);
    const u64* wc2  = reinterpret_cast<const u64*>(sWc);
    const u64* w1p  = reinterpret_cast<const u64*>(sW1);
    const u64* w2i  = reinterpret_cast<const u64*>(sW2i);
    const u64* bq2  = reinterpret_cast<const u64*>(sbq);
    const u64* bc2  = reinterpret_cast<const u64*>(sbc);
    const u64* b1p  = reinterpret_cast<const u64*>(sb1);
    const u64* b2pk = reinterpret_cast<const u64*>(sb2);
    const u64* th2  = reinterpret_cast<const u64*>(sth);
    const u64* g1pk = reinterpret_cast<const u64*>(sg1);
    const u64* be1p = reinterpret_cast<const u64*>(sbe1);
    const u64* g2pk = reinterpret_cast<const u64*>(sg2);
    const u64* be2p = reinterpret_cast<const u64*>(sbe2);

    float zf[4][8];                                   // FFN inputs for 4 tokens

    // ================= attention + LN1, one token-pair at a time =================
    #pragma unroll
    for (int p = 0; p < 2; p++) {
        const int tk0 = 2 * p;
        // ---- load 2 tokens ----
        float xv0[8], xv1[8];
        {
            const float4* xp = reinterpret_cast<const float4*>(x + (size_t)(base + tk0) * NE);
            float4 a = xp[0], b = xp[1], c = xp[2], d = xp[3];
            xv0[0] = a.x; xv0[1] = a.y; xv0[2] = a.z; xv0[3] = a.w;
            xv0[4] = b.x; xv0[5] = b.y; xv0[6] = b.z; xv0[7] = b.w;
            xv1[0] = c.x; xv1[1] = c.y; xv1[2] = c.z; xv1[3] = c.w;
            xv1[4] = d.x; xv1[5] = d.y; xv1[6] = d.z; xv1[7] = d.w;
        }
        // ---- q = x@Wq + bq ----
        u64 A0[4], A1[4];
        #pragma unroll
        for (int j = 0; j < 4; j++) { A0[j] = bq2[j]; A1[j] = bq2[j]; }
        #pragma unroll
        for (int k = 0; k < 8; k++) {
            u64 w0 = wq2[k * 4 + 0], w1_ = wq2[k * 4 + 1], w2_ = wq2[k * 4 + 2], w3_ = wq2[k * 4 + 3];
            const u64 xk0 = bcast2(xv0[k]), xk1 = bcast2(xv1[k]);
            A0[0] = fma2(xk0, w0, A0[0]);  A1[0] = fma2(xk1, w0, A1[0]);
            A0[1] = fma2(xk0, w1_, A0[1]); A1[1] = fma2(xk1, w1_, A1[1]);
            A0[2] = fma2(xk0, w2_, A0[2]); A1[2] = fma2(xk1, w2_, A1[2]);
            A0[3] = fma2(xk0, w3_, A0[3]); A1[3] = fma2(xk1, w3_, A1[3]);
        }
        // ---- ca = cos(q + theta) ; <Z> ----
        float z0a[8], z1a[8];
        {
            float ca0[8], ca1[8];
            #pragma unroll
            for (int j = 0; j < 4; j++) {
                u64 s0 = add2(A0[j], th2[j]);
                u64 s1 = add2(A1[j], th2[j]);
                float a, b;
                up2(s0, a, b); ca0[2 * j] = __cosf(a); ca0[2 * j + 1] = __cosf(b);
                up2(s1, a, b); ca1[2 * j] = __cosf(a); ca1[2 * j + 1] = __cosf(b);
            }
            float s0 = ca0[1] * ca0[2]; s0 *= ca0[3]; s0 *= ca0[4]; s0 *= ca0[5]; s0 *= ca0[6]; s0 *= ca0[7];
            float s1 = ca1[1] * ca1[2]; s1 *= ca1[3]; s1 *= ca1[4]; s1 *= ca1[5]; s1 *= ca1[6]; s1 *= ca1[7];
            z0a[0] = s0; z1a[0] = s1;
            z0a[1] = ca0[0] * ca0[1]; z1a[1] = ca1[0] * ca1[1];
            #pragma unroll
            for (int k = 2; k < 8; k++) { z0a[k] = z0a[k - 1] * ca0[k]; z1a[k] = z1a[k - 1] * ca1[k]; }
        }
        // ---- attn_out = z@Wc + bc ----
        #pragma unroll
        for (int j = 0; j < 4; j++) { A0[j] = bc2[j]; A1[j] = bc2[j]; }
        #pragma unroll
        for (int k = 0; k < 8; k++) {
            u64 w0 = wc2[k * 4 + 0], w1_ = wc2[k * 4 + 1], w2_ = wc2[k * 4 + 2], w3_ = wc2[k * 4 + 3];
            const u64 zk0 = bcast2(z0a[k]), zk1 = bcast2(z1a[k]);
            A0[0] = fma2(zk0, w0, A0[0]);  A1[0] = fma2(zk1, w0, A1[0]);
            A0[1] = fma2(zk0, w1_, A0[1]); A1[1] = fma2(zk1, w1_, A1[1]);
            A0[2] = fma2(zk0, w2_, A0[2]); A1[2] = fma2(zk1, w2_, A1[2]);
            A0[3] = fma2(zk0, w3_, A0[3]); A1[3] = fma2(zk1, w3_, A1[3]);
        }
        // ---- residual + LN1 ; stash x1 in smem ; zf ----
        u64 x1a[4], x1b[4];
        {
            u64 r0[4], r1[4];
            #pragma unroll
            for (int j = 0; j < 4; j++) {
                r0[j] = add2(A0[j], pack2(xv0[2 * j], xv0[2 * j + 1]));
                r1[j] = add2(A1[j], pack2(xv1[2 * j], xv1[2 * j + 1]));
            }
            ln8(r0, g1pk, be1p, x1a);
            ln8(r1, g1pk, be1p, x1b);
        }
        #pragma unroll
        for (int j = 0; j < 4; j++) {
            sx1[(tk0 + 0) * 4 + j][t] = x1a[j];
            sx1[(tk0 + 1) * 4 + j][t] = x1b[j];
        }
        #pragma unroll
        for (int j = 0; j < 4; j++) {
            float a, b;
            up2(x1a[j], a, b);
            zf[tk0 + 0][2 * j]     = sctf[2 * j]     * __cosf(a);
            zf[tk0 + 0][2 * j + 1] = sctf[2 * j + 1] * __cosf(b);
            up2(x1b[j], a, b);
            zf[tk0 + 1][2 * j]     = sctf[2 * j]     * __cosf(a);
            zf[tk0 + 1][2 * j + 1] = sctf[2 * j + 1] * __cosf(b);
        }
    }

    // ================= fused FFN over all 4 tokens, weights read once =================
    u64 f[4][8];
    #pragma unroll
    for (int tk = 0; tk < 4; tk++)
        #pragma unroll
        for (int j = 0; j < 8; j++) f[tk][j] = 0ULL;

    #pragma unroll
    for (int b = 0; b < 4; b++) {
        u64 h[4][4];
        #pragma unroll
        for (int ip = 0; ip < 4; ip++) {
            const u64 bb = b1p[b * 4 + ip];
            h[0][ip] = bb; h[1][ip] = bb; h[2][ip] = bb; h[3][ip] = bb;
        }
        #pragma unroll
        for (int j = 0; j < 8; j++) {
            u64 wa = w1p[j * 16 + b * 4 + 0], wb = w1p[j * 16 + b * 4 + 1];
            u64 wc_ = w1p[j * 16 + b * 4 + 2], wd = w1p[j * 16 + b * 4 + 3];
            #pragma unroll
            for (int tk = 0; tk < 4; tk++) {
                const u64 zb = bcast2(zf[tk][j]);
                h[tk][0] = fma2(zb, wa, h[tk][0]);
                h[tk][1] = fma2(zb, wb, h[tk][1]);
                h[tk][2] = fma2(zb, wc_, h[tk][2]);
                h[tk][3] = fma2(zb, wd, h[tk][3]);
            }
        }
        #pragma unroll
        for (int ip = 0; ip < 4; ip++) {
            const int p = b * 4 + ip;
            u64 hr[4];
            #pragma unroll
            for (int tk = 0; tk < 4; tk++) {
                float a, c;
                up2(h[tk][ip], a, c);
                hr[tk] = pack2(fmaxf(a, 0.f), fmaxf(c, 0.f));
            }
            #pragma unroll
            for (int j = 0; j < 8; j++) {
                const u64 w = w2i[p * 8 + j];
                f[0][j] = fma2(hr[0], w, f[0][j]);
                f[1][j] = fma2(hr[1], w, f[1][j]);
                f[2][j] = fma2(hr[2], w, f[2][j]);
                f[3][j] = fma2(hr[3], w, f[3][j]);
            }
        }
    }

    // ================= lane-fold + bias + residual ; LN2 ; store =================
    #pragma unroll
    for (int tk = 0; tk < 4; tk++) {
        float s[8];
        #pragma unroll
        for (int j = 0; j < 8; j++) {
            float a, b;
            up2(f[tk][j], a, b); s[j] = a + b;
        }
        u64 r[4], o[4];
        #pragma unroll
        for (int j = 0; j < 4; j++)
            r[j] = add2(add2(pack2(s[2 * j], s[2 * j + 1]), b2pk[j]), sx1[tk * 4 + j][t]);
        ln8(r, g2pk, be2p, o);
        float4* op = reinterpret_cast<float4*>(out + (size_t)(base + tk) * NE);
        float a, b, c, d;
        up2(o[0], a, b); up2(o[1], c, d); op[0] = make_float4(a, b, c, d);
        up2(o[2], a, b); up2(o[3], c, d); op[1] = make_float4(a, b, c, d);
    }
}

extern "C" void kernel_launch(void* const* d_in, const int* in_sizes, int n_in,
                              void* d_out, int out_size)
{
    const float* x          = (const float*)d_in[0];
    const float* Wq         = (const float*)d_in[1];
    const float* bq         = (const float*)d_in[2];
    const float* theta_attn = (const float*)d_in[3];
    const float* Wc         = (const float*)d_in[4];
    const float* bc         = (const float*)d_in[5];
    const float* g1         = (const float*)d_in[6];
    const float* beta1      = (const float*)d_in[7];
    const float* theta_ffn  = (const float*)d_in[8];
    const float* W1         = (const float*)d_in[9];
    const float* b1         = (const float*)d_in[10];
    const float* W2         = (const float*)d_in[11];
    const float* b2         = (const float*)d_in[12];
    const float* g2         = (const float*)d_in[13];
    const float* beta2      = (const float*)d_in[14];

    const int tokens = out_size / NE;                     // 1,048,576
    const int threads_needed = tokens / 4;                // 4 tokens per thread
    const int blocks = (threads_needed + TPB - 1) / TPB;  // 2048

    tbq_kernel<<<blocks, TPB>>>(x, Wq, bq, theta_attn, Wc, bc, g1, beta1,
                                theta_ffn, W1, b1, W2, b2, g2, beta2,
                                (float*)d_out, tokens);
}

// round 10
// speedup vs baseline: 1.1413x; 1.1413x over previous
#include <cuda_runtime.h>

#define NE 8
#define NF 32
#define EPSV 1e-5f
#define TPB 256

typedef unsigned long long u64;

__device__ __forceinline__ u64 bcast2(float v) {
    u64 r; asm("mov.b64 %0, {%1, %1};" : "=l"(r) : "f"(v)); return r;
}
__device__ __forceinline__ void up2(u64 v, float& a, float& b) {
    asm("mov.b64 {%0, %1}, %2;" : "=f"(a), "=f"(b) : "l"(v));
}
__device__ __forceinline__ u64 pack2(float a, float b) {
    u64 r; asm("mov.b64 %0, {%1, %2};" : "=l"(r) : "f"(a), "f"(b)); return r;
}
__device__ __forceinline__ u64 fma2(u64 a, u64 b, u64 c) {
    u64 d; asm("fma.rn.f32x2 %0, %1, %2, %3;" : "=l"(d) : "l"(a), "l"(b), "l"(c)); return d;
}
__device__ __forceinline__ u64 add2(u64 a, u64 b) {
    u64 d; asm("add.rn.f32x2 %0, %1, %2;" : "=l"(d) : "l"(a), "l"(b)); return d;
}
__device__ __forceinline__ u64 mul2(u64 a, u64 b) {
    u64 d; asm("mul.rn.f32x2 %0, %1, %2;" : "=l"(d) : "l"(a), "l"(b)); return d;
}
__device__ __forceinline__ float rsqrt_a(float v) {
    float r; asm("rsqrt.approx.f32 %0, %1;" : "=f"(r) : "f"(v)); return r;
}
// 128-bit shared load of two consecutive u64 (guaranteed LDS.128 broadcast)
__device__ __forceinline__ void lds2(const u64* p, u64& a, u64& b) {
    ulonglong2 v = *reinterpret_cast<const ulonglong2*>(p);
    a = v.x; b = v.y;
}

// LayerNorm over 8 elements held as 4 packed f32x2.
__device__ __forceinline__ void ln8(const u64 r[4], const u64 g[4], const u64 be[4], u64 o[4]) {
    u64 s = add2(add2(r[0], r[1]), add2(r[2], r[3]));
    float a, b; up2(s, a, b);
    const float m = (a + b) * 0.125f;
    const u64 nm = bcast2(-m);
    u64 d0 = add2(r[0], nm), d1 = add2(r[1], nm), d2 = add2(r[2], nm), d3 = add2(r[3], nm);
    u64 v2 = mul2(d0, d0);
    v2 = fma2(d1, d1, v2); v2 = fma2(d2, d2, v2); v2 = fma2(d3, d3, v2);
    up2(v2, a, b);
    const float inv = rsqrt_a((a + b) * 0.125f + EPSV);
    const u64 i2 = bcast2(inv);
    o[0] = fma2(mul2(d0, i2), g[0], be[0]);
    o[1] = fma2(mul2(d1, i2), g[1], be[1]);
    o[2] = fma2(mul2(d2, i2), g[2], be[2]);
    o[3] = fma2(mul2(d3, i2), g[3], be[3]);
}

__global__ __launch_bounds__(TPB, 2) void tbq_kernel(
    const float* __restrict__ x,
    const float* __restrict__ Wq,  const float* __restrict__ bq,
    const float* __restrict__ theta_attn,
    const float* __restrict__ Wc,  const float* __restrict__ bc,
    const float* __restrict__ g1,  const float* __restrict__ beta1,
    const float* __restrict__ theta_ffn,
    const float* __restrict__ W1,  const float* __restrict__ b1,
    const float* __restrict__ W2,  const float* __restrict__ b2,
    const float* __restrict__ g2,  const float* __restrict__ beta2,
    float* __restrict__ out, int tokens)
{
    __shared__ __align__(16) float sWq[64];    // [k][j]
    __shared__ __align__(16) float sWc[64];    // [k][j]
    __shared__ __align__(16) float sW1[256];   // original [j][i], hidden contiguous
    __shared__ __align__(16) float sW2i[256];  // [p][j][half] = W2[2p+half][j]
    __shared__ __align__(16) float sbq[8], sbc[8], sth[8], sctf[8];
    __shared__ __align__(16) float sb1[32], sb2[8];
    __shared__ __align__(16) float sg1[8], sbe1[8], sg2[8], sbe2[8];

    const int t = threadIdx.x;
    if (t < 64) { sWq[t] = Wq[t]; sWc[t] = Wc[t]; }
    sW1[t] = W1[t];
    {
        int p = t >> 4, r = t & 15, j = r >> 1, half = r & 1;
        sW2i[t] = W2[(2 * p + half) * NE + j];
    }
    if (t < 32) sb1[t] = b1[t];
    if (t < 8) {
        sbq[t] = bq[t];  sbc[t] = bc[t];
        sth[t] = theta_attn[t];
        sctf[t] = __cosf(theta_ffn[t]);
        sb2[t] = b2[t];
        sg1[t] = g1[t];  sbe1[t] = beta1[t];
        sg2[t] = g2[t];  sbe2[t] = beta2[t];
    }
    __syncthreads();

    const int base = (blockIdx.x * TPB + t) * 2;      // 2 tokens per thread
    if (base >= tokens) return;

    const u64* wq2  = reinterpret_cast<const u64*>(sWq);
    const u64* wc2  = reinterpret_cast<const u64*>(sWc);
    const u64* w1p  = reinterpret_cast<const u64*>(sW1);
    const u64* w2i  = reinterpret_cast<const u64*>(sW2i);
    const u64* bq2  = reinterpret_cast<const u64*>(sbq);
    const u64* bc2  = reinterpret_cast<const u64*>(sbc);
    const u64* b1p  = reinterpret_cast<const u64*>(sb1);
    const u64* b2pk = reinterpret_cast<const u64*>(sb2);
    const u64* th2  = reinterpret_cast<const u64*>(sth);
    const u64* g1pk = reinterpret_cast<const u64*>(sg1);
    const u64* be1p = reinterpret_cast<const u64*>(sbe1);
    const u64* g2pk = reinterpret_cast<const u64*>(sg2);
    const u64* be2p = reinterpret_cast<const u64*>(sbe2);

    // ---- load 2 tokens (16 floats = 4 LDG.128) ----
    float xv0[8], xv1[8];
    {
        const float4* xp = reinterpret_cast<const float4*>(x + (size_t)base * NE);
        float4 a = xp[0], b = xp[1], c = xp[2], d = xp[3];
        xv0[0] = a.x; xv0[1] = a.y; xv0[2] = a.z; xv0[3] = a.w;
        xv0[4] = b.x; xv0[5] = b.y; xv0[6] = b.z; xv0[7] = b.w;
        xv1[0] = c.x; xv1[1] = c.y; xv1[2] = c.z; xv1[3] = c.w;
        xv1[4] = d.x; xv1[5] = d.y; xv1[6] = d.z; xv1[7] = d.w;
    }

    // ---- preload packed params via LDS.128 ----
    u64 gA[4], gB[4];                                  // generic scratch pairs

    // ---- q = x@Wq + bq for both tokens, weight rows via LDS.128 ----
    u64 A0[4], A1[4];
    lds2(&bq2[0], gA[0], gA[1]); lds2(&bq2[2], gA[2], gA[3]);
    #pragma unroll
    for (int j = 0; j < 4; j++) { A0[j] = gA[j]; A1[j] = gA[j]; }
    #pragma unroll
    for (int k = 0; k < 8; k++) {
        u64 w0, w1_, w2_, w3_;
        lds2(&wq2[k * 4 + 0], w0, w1_);
        lds2(&wq2[k * 4 + 2], w2_, w3_);
        const u64 xk0 = bcast2(xv0[k]), xk1 = bcast2(xv1[k]);
        A0[0] = fma2(xk0, w0, A0[0]);  A1[0] = fma2(xk1, w0, A1[0]);
        A0[1] = fma2(xk0, w1_, A0[1]); A1[1] = fma2(xk1, w1_, A1[1]);
        A0[2] = fma2(xk0, w2_, A0[2]); A1[2] = fma2(xk1, w2_, A1[2]);
        A0[3] = fma2(xk0, w3_, A0[3]); A1[3] = fma2(xk1, w3_, A1[3]);
    }

    // ---- ca = cos(q + theta) ; <Z> via prefix/suffix products ----
    float z0a[8], z1a[8];
    {
        lds2(&th2[0], gA[0], gA[1]); lds2(&th2[2], gA[2], gA[3]);
        float ca0[8], ca1[8];
        #pragma unroll
        for (int j = 0; j < 4; j++) {
            u64 s0 = add2(A0[j], gA[j]);
            u64 s1 = add2(A1[j], gA[j]);
            float a, b;
            up2(s0, a, b); ca0[2 * j] = __cosf(a); ca0[2 * j + 1] = __cosf(b);
            up2(s1, a, b); ca1[2 * j] = __cosf(a); ca1[2 * j + 1] = __cosf(b);
        }
        float s0 = ca0[1] * ca0[2]; s0 *= ca0[3]; s0 *= ca0[4]; s0 *= ca0[5]; s0 *= ca0[6]; s0 *= ca0[7];
        float s1 = ca1[1] * ca1[2]; s1 *= ca1[3]; s1 *= ca1[4]; s1 *= ca1[5]; s1 *= ca1[6]; s1 *= ca1[7];
        z0a[0] = s0; z1a[0] = s1;
        z0a[1] = ca0[0] * ca0[1]; z1a[1] = ca1[0] * ca1[1];
        #pragma unroll
        for (int k = 2; k < 8; k++) { z0a[k] = z0a[k - 1] * ca0[k]; z1a[k] = z1a[k - 1] * ca1[k]; }
    }

    // ---- attn_out = z@Wc + bc, weight rows via LDS.128 ----
    lds2(&bc2[0], gA[0], gA[1]); lds2(&bc2[2], gA[2], gA[3]);
    #pragma unroll
    for (int j = 0; j < 4; j++) { A0[j] = gA[j]; A1[j] = gA[j]; }
    #pragma unroll
    for (int k = 0; k < 8; k++) {
        u64 w0, w1_, w2_, w3_;
        lds2(&wc2[k * 4 + 0], w0, w1_);
        lds2(&wc2[k * 4 + 2], w2_, w3_);
        const u64 zk0 = bcast2(z0a[k]), zk1 = bcast2(z1a[k]);
        A0[0] = fma2(zk0, w0, A0[0]);  A1[0] = fma2(zk1, w0, A1[0]);
        A0[1] = fma2(zk0, w1_, A0[1]); A1[1] = fma2(zk1, w1_, A1[1]);
        A0[2] = fma2(zk0, w2_, A0[2]); A1[2] = fma2(zk1, w2_, A1[2]);
        A0[3] = fma2(zk0, w3_, A0[3]); A1[3] = fma2(zk1, w3_, A1[3]);
    }

    // ---- residual + LN1 (packed params via LDS.128) ----
    u64 x1p0[4], x1p1[4];
    {
        u64 r0[4], r1[4];
        #pragma unroll
        for (int j = 0; j < 4; j++) {
            r0[j] = add2(A0[j], pack2(xv0[2 * j], xv0[2 * j + 1]));
            r1[j] = add2(A1[j], pack2(xv1[2 * j], xv1[2 * j + 1]));
        }
        lds2(&g1pk[0], gA[0], gA[1]); lds2(&g1pk[2], gA[2], gA[3]);
        lds2(&be1p[0], gB[0], gB[1]); lds2(&be1p[2], gB[2], gB[3]);
        ln8(r0, gA, gB, x1p0);
        ln8(r1, gA, gB, x1p1);
    }

    // ---- zf = cos(theta_ffn)*cos(x1) ----
    float zf0[8], zf1[8];
    #pragma unroll
    for (int j = 0; j < 4; j++) {
        float a, b;
        up2(x1p0[j], a, b);
        zf0[2 * j]     = sctf[2 * j]     * __cosf(a);
        zf0[2 * j + 1] = sctf[2 * j + 1] * __cosf(b);
        up2(x1p1[j], a, b);
        zf1[2 * j]     = sctf[2 * j]     * __cosf(a);
        zf1[2 * j + 1] = sctf[2 * j + 1] * __cosf(b);
    }

    // ---- fused FFN: 4 blocks of 4 hidden-pairs; all weight reads LDS.128 ----
    u64 f0[8], f1[8];
    #pragma unroll
    for (int j = 0; j < 8; j++) { f0[j] = 0ULL; f1[j] = 0ULL; }
    #pragma unroll
    for (int b = 0; b < 4; b++) {
        u64 h0[4], h1[4];
        lds2(&b1p[b * 4 + 0], gA[0], gA[1]); lds2(&b1p[b * 4 + 2], gA[2], gA[3]);
        #pragma unroll
        for (int ip = 0; ip < 4; ip++) { h0[ip] = gA[ip]; h1[ip] = gA[ip]; }
        #pragma unroll
        for (int j = 0; j < 8; j++) {
            u64 wa, wb, wc_, wd;
            lds2(&w1p[j * 16 + b * 4 + 0], wa, wb);
            lds2(&w1p[j * 16 + b * 4 + 2], wc_, wd);
            const u64 zb0 = bcast2(zf0[j]), zb1 = bcast2(zf1[j]);
            h0[0] = fma2(zb0, wa, h0[0]);  h1[0] = fma2(zb1, wa, h1[0]);
            h0[1] = fma2(zb0, wb, h0[1]);  h1[1] = fma2(zb1, wb, h1[1]);
            h0[2] = fma2(zb0, wc_, h0[2]); h1[2] = fma2(zb1, wc_, h1[2]);
            h0[3] = fma2(zb0, wd, h0[3]);  h1[3] = fma2(zb1, wd, h1[3]);
        }
        #pragma unroll
        for (int ip = 0; ip < 4; ip++) {
            const int p = b * 4 + ip;
            float a, c;
            up2(h0[ip], a, c);
            const u64 hr0 = pack2(fmaxf(a, 0.f), fmaxf(c, 0.f));
            up2(h1[ip], a, c);
            const u64 hr1 = pack2(fmaxf(a, 0.f), fmaxf(c, 0.f));
            #pragma unroll
            for (int c2 = 0; c2 < 4; c2++) {
                u64 wa, wb;
                lds2(&w2i[p * 8 + 2 * c2], wa, wb);
                f0[2 * c2]     = fma2(hr0, wa, f0[2 * c2]);
                f1[2 * c2]     = fma2(hr1, wa, f1[2 * c2]);
                f0[2 * c2 + 1] = fma2(hr0, wb, f0[2 * c2 + 1]);
                f1[2 * c2 + 1] = fma2(hr1, wb, f1[2 * c2 + 1]);
            }
        }
    }

    // ---- lane-fold + bias + residual ; LN2 ; store as 4x STG.128 ----
    u64 o0[4], o1[4];
    {
        float s0[8], s1[8];
        #pragma unroll
        for (int j = 0; j < 8; j++) {
            float a, b;
            up2(f0[j], a, b); s0[j] = a + b;
            up2(f1[j], a, b); s1[j] = a + b;
        }
        u64 bp[4];
        lds2(&b2pk[0], bp[0], bp[1]); lds2(&b2pk[2], bp[2], bp[3]);
        u64 r0[4], r1[4];
        #pragma unroll
        for (int j = 0; j < 4; j++) {
            r0[j] = add2(add2(pack2(s0[2 * j], s0[2 * j + 1]), bp[j]), x1p0[j]);
            r1[j] = add2(add2(pack2(s1[2 * j], s1[2 * j + 1]), bp[j]), x1p1[j]);
        }
        lds2(&g2pk[0], gA[0], gA[1]); lds2(&g2pk[2], gA[2], gA[3]);
        lds2(&be2p[0], gB[0], gB[1]); lds2(&be2p[2], gB[2], gB[3]);
        ln8(r0, gA, gB, o0);
        ln8(r1, gA, gB, o1);
    }
    {
        float4* op = reinterpret_cast<float4*>(out + (size_t)base * NE);
        float a, b, c, d;
        up2(o0[0], a, b); up2(o0[1], c, d); op[0] = make_float4(a, b, c, d);
        up2(o0[2], a, b); up2(o0[3], c, d); op[1] = make_float4(a, b, c, d);
        up2(o1[0], a, b); up2(o1[1], c, d); op[2] = make_float4(a, b, c, d);
        up2(o1[2], a, b); up2(o1[3], c, d); op[3] = make_float4(a, b, c, d);
    }
}

extern "C" void kernel_launch(void* const* d_in, const int* in_sizes, int n_in,
                              void* d_out, int out_size)
{
    const float* x          = (const float*)d_in[0];
    const float* Wq         = (const float*)d_in[1];
    const float* bq         = (const float*)d_in[2];
    const float* theta_attn = (const float*)d_in[3];
    const float* Wc         = (const float*)d_in[4];
    const float* bc         = (const float*)d_in[5];
    const float* g1         = (const float*)d_in[6];
    const float* beta1      = (const float*)d_in[7];
    const float* theta_ffn  = (const float*)d_in[8];
    const float* W1         = (const float*)d_in[9];
    const float* b1         = (const float*)d_in[10];
    const float* W2         = (const float*)d_in[11];
    const float* b2         = (const float*)d_in[12];
    const float* g2         = (const float*)d_in[13];
    const float* beta2      = (const float*)d_in[14];

    const int tokens = out_size / NE;                     // 1,048,576
    const int threads_needed = tokens / 2;                // 2 tokens per thread
    const int blocks = (threads_needed + TPB - 1) / TPB;  // 2048

    tbq_kernel<<<blocks, TPB>>>(x, Wq, bq, theta_attn, Wc, bc, g1, beta1,
                                theta_ffn, W1, b1, W2, b2, g2, beta2,
                                (float*)d_out, tokens);
}

// round 11
// speedup vs baseline: 1.4771x; 1.2943x over previous
#include <cuda_runtime.h>

#define NE 8
#define NF 32
#define EPSV 1e-5f
#define TPB 256

typedef unsigned long long u64;

// ---- constant weight buffer: 186 ulonglong2 = 744 floats ----
// u64-index layout:
//   0..31   wq2 [k*4+c]          32..63  wc2
//   64..191 w1p [j*16+i]         192..319 w2i [p*8+j]
//   320..323 bq2   324..327 bc2  328..331 th2  332..335 ctf
//   336..351 b1p   352..355 b2pk
//   356..359 g1pk  360..363 be1p 364..367 g2pk 368..371 be2p
__constant__ ulonglong2 cb[186];
__device__ float d_stage[744];

__device__ __forceinline__ u64 cu(int i) {            // compile-time u64 index
    ulonglong2 v = cb[i >> 1]; return (i & 1) ? v.y : v.x;
}
__device__ __forceinline__ void cu2(int i, u64& a, u64& b) {  // i even
    ulonglong2 v = cb[i >> 1]; a = v.x; b = v.y;
}

__device__ __forceinline__ u64 bcast2(float v) {
    u64 r; asm("mov.b64 %0, {%1, %1};" : "=l"(r) : "f"(v)); return r;
}
__device__ __forceinline__ void up2(u64 v, float& a, float& b) {
    asm("mov.b64 {%0, %1}, %2;" : "=f"(a), "=f"(b) : "l"(v));
}
__device__ __forceinline__ u64 pack2(float a, float b) {
    u64 r; asm("mov.b64 %0, {%1, %2};" : "=l"(r) : "f"(a), "f"(b)); return r;
}
__device__ __forceinline__ u64 fma2(u64 a, u64 b, u64 c) {
    u64 d; asm("fma.rn.f32x2 %0, %1, %2, %3;" : "=l"(d) : "l"(a), "l"(b), "l"(c)); return d;
}
__device__ __forceinline__ u64 add2(u64 a, u64 b) {
    u64 d; asm("add.rn.f32x2 %0, %1, %2;" : "=l"(d) : "l"(a), "l"(b)); return d;
}
__device__ __forceinline__ u64 mul2(u64 a, u64 b) {
    u64 d; asm("mul.rn.f32x2 %0, %1, %2;" : "=l"(d) : "l"(a), "l"(b)); return d;
}
__device__ __forceinline__ float rsqrt_a(float v) {
    float r; asm("rsqrt.approx.f32 %0, %1;" : "=f"(r) : "f"(v)); return r;
}

// LayerNorm over 8 elements held as 4 packed f32x2; gb = u64 base of gamma, bb = of beta.
__device__ __forceinline__ void ln8c(const u64 r[4], int gb, int bb, u64 o[4]) {
    u64 s = add2(add2(r[0], r[1]), add2(r[2], r[3]));
    float a, b; up2(s, a, b);
    const float m = (a + b) * 0.125f;
    const u64 nm = bcast2(-m);
    u64 d0 = add2(r[0], nm), d1 = add2(r[1], nm), d2 = add2(r[2], nm), d3 = add2(r[3], nm);
    u64 v2 = mul2(d0, d0);
    v2 = fma2(d1, d1, v2); v2 = fma2(d2, d2, v2); v2 = fma2(d3, d3, v2);
    up2(v2, a, b);
    const float inv = rsqrt_a((a + b) * 0.125f + EPSV);
    const u64 i2 = bcast2(inv);
    o[0] = fma2(mul2(d0, i2), cu(gb + 0), cu(bb + 0));
    o[1] = fma2(mul2(d1, i2), cu(gb + 1), cu(bb + 1));
    o[2] = fma2(mul2(d2, i2), cu(gb + 2), cu(bb + 2));
    o[3] = fma2(mul2(d3, i2), cu(gb + 3), cu(bb + 3));
}

// ---- pack kernel: gather + preprocess all params into staging buffer ----
__global__ void pack_kernel(
    const float* __restrict__ Wq, const float* __restrict__ Wc,
    const float* __restrict__ W1, const float* __restrict__ W2,
    const float* __restrict__ bq, const float* __restrict__ bc,
    const float* __restrict__ th, const float* __restrict__ thf,
    const float* __restrict__ b1, const float* __restrict__ b2,
    const float* __restrict__ g1, const float* __restrict__ be1,
    const float* __restrict__ g2, const float* __restrict__ be2)
{
    int t = threadIdx.x;                                   // 256 threads
    if (t < 64) { d_stage[t] = Wq[t]; d_stage[64 + t] = Wc[t]; }
    d_stage[128 + t] = W1[t];                              // original [j][i]
    {   // W2 interleave: [p][j][half] = W2[2p+half][j]
        int p = t >> 4, r = t & 15, j = r >> 1, half = r & 1;
        d_stage[384 + t] = W2[(2 * p + half) * NE + j];
    }
    if (t < 32) d_stage[672 + t] = b1[t];
    if (t < 8) {
        d_stage[640 + t] = bq[t];
        d_stage[648 + t] = bc[t];
        d_stage[656 + t] = th[t];
        d_stage[664 + t] = __cosf(thf[t]);                 // fold cos(theta_ffn)
        d_stage[704 + t] = b2[t];
        d_stage[712 + t] = g1[t];
        d_stage[720 + t] = be1[t];
        d_stage[728 + t] = g2[t];
        d_stage[736 + t] = be2[t];
    }
}

__global__ __launch_bounds__(TPB, 2) void tbq_kernel(
    const float* __restrict__ x, float* __restrict__ out, int tokens)
{
    const int t = threadIdx.x;
    const int base = (blockIdx.x * TPB + t) * 2;          // 2 tokens per thread
    if (base >= tokens) return;

    // ---- load 2 tokens (16 floats = 4 LDG.128) ----
    float xv0[8], xv1[8];
    {
        const float4* xp = reinterpret_cast<const float4*>(x + (size_t)base * NE);
        float4 a = xp[0], b = xp[1], c = xp[2], d = xp[3];
        xv0[0] = a.x; xv0[1] = a.y; xv0[2] = a.z; xv0[3] = a.w;
        xv0[4] = b.x; xv0[5] = b.y; xv0[6] = b.z; xv0[7] = b.w;
        xv1[0] = c.x; xv1[1] = c.y; xv1[2] = c.z; xv1[3] = c.w;
        xv1[4] = d.x; xv1[5] = d.y; xv1[6] = d.z; xv1[7] = d.w;
    }

    // ---- q = x@Wq + bq for both tokens, weights via constant cache ----
    u64 A0[4], A1[4];
    #pragma unroll
    for (int j = 0; j < 4; j++) { u64 b_ = cu(320 + j); A0[j] = b_; A1[j] = b_; }
    #pragma unroll
    for (int k = 0; k < 8; k++) {
        u64 w0, w1_, w2_, w3_;
        cu2(k * 4 + 0, w0, w1_);
        cu2(k * 4 + 2, w2_, w3_);
        const u64 xk0 = bcast2(xv0[k]), xk1 = bcast2(xv1[k]);
        A0[0] = fma2(xk0, w0, A0[0]);  A1[0] = fma2(xk1, w0, A1[0]);
        A0[1] = fma2(xk0, w1_, A0[1]); A1[1] = fma2(xk1, w1_, A1[1]);
        A0[2] = fma2(xk0, w2_, A0[2]); A1[2] = fma2(xk1, w2_, A1[2]);
        A0[3] = fma2(xk0, w3_, A0[3]); A1[3] = fma2(xk1, w3_, A1[3]);
    }

    // ---- ca = cos(q + theta) ; <Z> via prefix/suffix products ----
    float z0a[8], z1a[8];
    {
        float ca0[8], ca1[8];
        #pragma unroll
        for (int j = 0; j < 4; j++) {
            const u64 thj = cu(328 + j);
            u64 s0 = add2(A0[j], thj);
            u64 s1 = add2(A1[j], thj);
            float a, b;
            up2(s0, a, b); ca0[2 * j] = __cosf(a); ca0[2 * j + 1] = __cosf(b);
            up2(s1, a, b); ca1[2 * j] = __cosf(a); ca1[2 * j + 1] = __cosf(b);
        }
        float s0 = ca0[1] * ca0[2]; s0 *= ca0[3]; s0 *= ca0[4]; s0 *= ca0[5]; s0 *= ca0[6]; s0 *= ca0[7];
        float s1 = ca1[1] * ca1[2]; s1 *= ca1[3]; s1 *= ca1[4]; s1 *= ca1[5]; s1 *= ca1[6]; s1 *= ca1[7];
        z0a[0] = s0; z1a[0] = s1;
        z0a[1] = ca0[0] * ca0[1]; z1a[1] = ca1[0] * ca1[1];
        #pragma unroll
        for (int k = 2; k < 8; k++) { z0a[k] = z0a[k - 1] * ca0[k]; z1a[k] = z1a[k - 1] * ca1[k]; }
    }

    // ---- attn_out = z@Wc + bc ----
    #pragma unroll
    for (int j = 0; j < 4; j++) { u64 b_ = cu(324 + j); A0[j] = b_; A1[j] = b_; }
    #pragma unroll
    for (int k = 0; k < 8; k++) {
        u64 w0, w1_, w2_, w3_;
        cu2(32 + k * 4 + 0, w0, w1_);
        cu2(32 + k * 4 + 2, w2_, w3_);
        const u64 zk0 = bcast2(z0a[k]), zk1 = bcast2(z1a[k]);
        A0[0] = fma2(zk0, w0, A0[0]);  A1[0] = fma2(zk1, w0, A1[0]);
        A0[1] = fma2(zk0, w1_, A0[1]); A1[1] = fma2(zk1, w1_, A1[1]);
        A0[2] = fma2(zk0, w2_, A0[2]); A1[2] = fma2(zk1, w2_, A1[2]);
        A0[3] = fma2(zk0, w3_, A0[3]); A1[3] = fma2(zk1, w3_, A1[3]);
    }

    // ---- residual + LN1 ----
    u64 x1p0[4], x1p1[4];
    {
        u64 r0[4], r1[4];
        #pragma unroll
        for (int j = 0; j < 4; j++) {
            r0[j] = add2(A0[j], pack2(xv0[2 * j], xv0[2 * j + 1]));
            r1[j] = add2(A1[j], pack2(xv1[2 * j], xv1[2 * j + 1]));
        }
        ln8c(r0, 356, 360, x1p0);
        ln8c(r1, 356, 360, x1p1);
    }

    // ---- zf = cos(theta_ffn)*cos(x1)  (ctf prefolded in constant) ----
    float zf0[8], zf1[8];
    #pragma unroll
    for (int j = 0; j < 4; j++) {
        float c0, c1, a, b;
        up2(cu(332 + j), c0, c1);
        up2(x1p0[j], a, b);
        zf0[2 * j]     = c0 * __cosf(a);
        zf0[2 * j + 1] = c1 * __cosf(b);
        up2(x1p1[j], a, b);
        zf1[2 * j]     = c0 * __cosf(a);
        zf1[2 * j + 1] = c1 * __cosf(b);
    }

    // ---- fused FFN: 4 blocks of 4 hidden-pairs; weights via constant cache ----
    u64 f0[8], f1[8];
    #pragma unroll
    for (int j = 0; j < 8; j++) { f0[j] = 0ULL; f1[j] = 0ULL; }
    #pragma unroll
    for (int b = 0; b < 4; b++) {
        u64 h0[4], h1[4];
        #pragma unroll
        for (int ip = 0; ip < 4; ip++) { u64 bb = cu(336 + b * 4 + ip); h0[ip] = bb; h1[ip] = bb; }
        #pragma unroll
        for (int j = 0; j < 8; j++) {
            u64 wa, wb, wc_, wd;
            cu2(64 + j * 16 + b * 4 + 0, wa, wb);
            cu2(64 + j * 16 + b * 4 + 2, wc_, wd);
            const u64 zb0 = bcast2(zf0[j]), zb1 = bcast2(zf1[j]);
            h0[0] = fma2(zb0, wa, h0[0]);  h1[0] = fma2(zb1, wa, h1[0]);
            h0[1] = fma2(zb0, wb, h0[1]);  h1[1] = fma2(zb1, wb, h1[1]);
            h0[2] = fma2(zb0, wc_, h0[2]); h1[2] = fma2(zb1, wc_, h1[2]);
            h0[3] = fma2(zb0, wd, h0[3]);  h1[3] = fma2(zb1, wd, h1[3]);
        }
        #pragma unroll
        for (int ip = 0; ip < 4; ip++) {
            const int p = b * 4 + ip;
            float a, c;
            up2(h0[ip], a, c);
            const u64 hr0 = pack2(fmaxf(a, 0.f), fmaxf(c, 0.f));
            up2(h1[ip], a, c);
            const u64 hr1 = pack2(fmaxf(a, 0.f), fmaxf(c, 0.f));
            #pragma unroll
            for (int c2 = 0; c2 < 4; c2++) {
                u64 wa, wb;
                cu2(192 + p * 8 + 2 * c2, wa, wb);
                f0[2 * c2]     = fma2(hr0, wa, f0[2 * c2]);
                f1[2 * c2]     = fma2(hr1, wa, f1[2 * c2]);
                f0[2 * c2 + 1] = fma2(hr0, wb, f0[2 * c2 + 1]);
                f1[2 * c2 + 1] = fma2(hr1, wb, f1[2 * c2 + 1]);
            }
        }
    }

    // ---- lane-fold + bias + residual ; LN2 ; store as 4x STG.128 ----
    u64 o0[4], o1[4];
    {
        float s0[8], s1[8];
        #pragma unroll
        for (int j = 0; j < 8; j++) {
            float a, b;
            up2(f0[j], a, b); s0[j] = a + b;
            up2(f1[j], a, b); s1[j] = a + b;
        }
        u64 r0[4], r1[4];
        #pragma unroll
        for (int j = 0; j < 4; j++) {
            const u64 bp = cu(352 + j);
            r0[j] = add2(add2(pack2(s0[2 * j], s0[2 * j + 1]), bp), x1p0[j]);
            r1[j] = add2(add2(pack2(s1[2 * j], s1[2 * j + 1]), bp), x1p1[j]);
        }
        ln8c(r0, 364, 368, o0);
        ln8c(r1, 364, 368, o1);
    }
    {
        float4* op = reinterpret_cast<float4*>(out + (size_t)base * NE);
        float a, b, c, d;
        up2(o0[0], a, b); up2(o0[1], c, d); op[0] = make_float4(a, b, c, d);
        up2(o0[2], a, b); up2(o0[3], c, d); op[1] = make_float4(a, b, c, d);
        up2(o1[0], a, b); up2(o1[1], c, d); op[2] = make_float4(a, b, c, d);
        up2(o1[2], a, b); up2(o1[3], c, d); op[3] = make_float4(a, b, c, d);
    }
}

extern "C" void kernel_launch(void* const* d_in, const int* in_sizes, int n_in,
                              void* d_out, int out_size)
{
    const float* x          = (const float*)d_in[0];
    const float* Wq         = (const float*)d_in[1];
    const float* bq         = (const float*)d_in[2];
    const float* theta_attn = (const float*)d_in[3];
    const float* Wc         = (const float*)d_in[4];
    const float* bc         = (const float*)d_in[5];
    const float* g1         = (const float*)d_in[6];
    const float* beta1      = (const float*)d_in[7];
    const float* theta_ffn  = (const float*)d_in[8];
    const float* W1         = (const float*)d_in[9];
    const float* b1         = (const float*)d_in[10];
    const float* W2         = (const float*)d_in[11];
    const float* b2         = (const float*)d_in[12];
    const float* g2         = (const float*)d_in[13];
    const float* beta2      = (const float*)d_in[14];

    // 1) gather + preprocess weights into staging (device global)
    pack_kernel<<<1, 256>>>(Wq, Wc, W1, W2, bq, bc, theta_attn, theta_ffn,
                            b1, b2, g1, beta1, g2, beta2);

    // 2) one D2D copy staging -> __constant__ (graph-capturable memcpy node)
    void* src = nullptr;
    cudaGetSymbolAddress(&src, d_stage);
    cudaMemcpyToSymbolAsync(cb, src, 744 * sizeof(float), 0,
                            cudaMemcpyDeviceToDevice, 0);

    // 3) main kernel
    const int tokens = out_size / NE;                     // 1,048,576
    const int threads_needed = tokens / 2;                // 2 tokens per thread
    const int blocks = (threads_needed + TPB - 1) / TPB;  // 2048
    tbq_kernel<<<blocks, TPB>>>(x, (float*)d_out, tokens);
}

// round 13
// speedup vs baseline: 1.4928x; 1.0106x over previous
#include <cuda_runtime.h>

#define NE 8
#define NF 32
#define EPSV 1e-5f
#define TPB 256

typedef unsigned long long u64;

// ---- constant weight buffer: 186 ulonglong2 = 744 floats ----
// u64-index layout:
//   0..31   wq2 [k*4+c]          32..63  wc2
//   64..191 w1p [j*16+i]         192..319 w2i [p*8+j]
//   320..323 bq2   324..327 bc2  328..331 th2  332..335 ctf
//   336..351 b1p   352..355 b2pk
//   356..359 g1pk  360..363 be1p 364..367 g2pk 368..371 be2p
__constant__ ulonglong2 cb[186];
__device__ float d_stage[744];

__device__ __forceinline__ u64 cu(int i) {            // compile-time u64 index
    ulonglong2 v = cb[i >> 1]; return (i & 1) ? v.y : v.x;
}
__device__ __forceinline__ void cu2(int i, u64& a, u64& b) {  // i even
    ulonglong2 v = cb[i >> 1]; a = v.x; b = v.y;
}

__device__ __forceinline__ u64 bcast2(float v) {
    u64 r; asm("mov.b64 %0, {%1, %1};" : "=l"(r) : "f"(v)); return r;
}
__device__ __forceinline__ void up2(u64 v, float& a, float& b) {
    asm("mov.b64 {%0, %1}, %2;" : "=f"(a), "=f"(b) : "l"(v));
}
__device__ __forceinline__ u64 pack2(float a, float b) {
    u64 r; asm("mov.b64 %0, {%1, %2};" : "=l"(r) : "f"(a), "f"(b)); return r;
}
__device__ __forceinline__ u64 fma2(u64 a, u64 b, u64 c) {
    u64 d; asm("fma.rn.f32x2 %0, %1, %2, %3;" : "=l"(d) : "l"(a), "l"(b), "l"(c)); return d;
}
__device__ __forceinline__ u64 add2(u64 a, u64 b) {
    u64 d; asm("add.rn.f32x2 %0, %1, %2;" : "=l"(d) : "l"(a), "l"(b)); return d;
}
__device__ __forceinline__ u64 mul2(u64 a, u64 b) {
    u64 d; asm("mul.rn.f32x2 %0, %1, %2;" : "=l"(d) : "l"(a), "l"(b)); return d;
}
__device__ __forceinline__ float rsqrt_a(float v) {
    float r; asm("rsqrt.approx.f32 %0, %1;" : "=f"(r) : "f"(v)); return r;
}

// LayerNorm over 8 elements held as 4 packed f32x2; gb = u64 base of gamma, bb = of beta.
__device__ __forceinline__ void ln8c(const u64 r[4], int gb, int bb, u64 o[4]) {
    u64 s = add2(add2(r[0], r[1]), add2(r[2], r[3]));
    float a, b; up2(s, a, b);
    const float m = (a + b) * 0.125f;
    const u64 nm = bcast2(-m);
    u64 d0 = add2(r[0], nm), d1 = add2(r[1], nm), d2 = add2(r[2], nm), d3 = add2(r[3], nm);
    u64 v2 = mul2(d0, d0);
    v2 = fma2(d1, d1, v2); v2 = fma2(d2, d2, v2); v2 = fma2(d3, d3, v2);
    up2(v2, a, b);
    const float inv = rsqrt_a((a + b) * 0.125f + EPSV);
    const u64 i2 = bcast2(inv);
    o[0] = fma2(mul2(d0, i2), cu(gb + 0), cu(bb + 0));
    o[1] = fma2(mul2(d1, i2), cu(gb + 1), cu(bb + 1));
    o[2] = fma2(mul2(d2, i2), cu(gb + 2), cu(bb + 2));
    o[3] = fma2(mul2(d3, i2), cu(gb + 3), cu(bb + 3));
}

// ---- pack kernel: gather + preprocess all params into staging buffer ----
__global__ void pack_kernel(
    const float* __restrict__ Wq, const float* __restrict__ Wc,
    const float* __restrict__ W1, const float* __restrict__ W2,
    const float* __restrict__ bq, const float* __restrict__ bc,
    const float* __restrict__ th, const float* __restrict__ thf,
    const float* __restrict__ b1, const float* __restrict__ b2,
    const float* __restrict__ g1, const float* __restrict__ be1,
    const float* __restrict__ g2, const float* __restrict__ be2)
{
    int t = threadIdx.x;                                   // 256 threads
    if (t < 64) { d_stage[t] = Wq[t]; d_stage[64 + t] = Wc[t]; }
    d_stage[128 + t] = W1[t];                              // original [j][i]
    {   // W2 interleave: [p][j][half] = W2[2p+half][j]
        int p = t >> 4, r = t & 15, j = r >> 1, half = r & 1;
        d_stage[384 + t] = W2[(2 * p + half) * NE + j];
    }
    if (t < 32) d_stage[672 + t] = b1[t];
    if (t < 8) {
        d_stage[640 + t] = bq[t];
        d_stage[648 + t] = bc[t];
        d_stage[656 + t] = th[t];
        d_stage[664 + t] = __cosf(thf[t]);                 // fold cos(theta_ffn)
        d_stage[704 + t] = b2[t];
        d_stage[712 + t] = g1[t];
        d_stage[720 + t] = be1[t];
        d_stage[728 + t] = g2[t];
        d_stage[736 + t] = be2[t];
    }
}

__global__ __launch_bounds__(TPB, 4) void tbq_kernel(
    const float* __restrict__ x, float* __restrict__ out, int tokens)
{
    const int tok = blockIdx.x * TPB + threadIdx.x;       // 1 token per thread
    if (tok >= tokens) return;

    // ---- load token (8 floats = 2 LDG.128) ----
    float xv[8];
    {
        const float4* xp = reinterpret_cast<const float4*>(x + (size_t)tok * NE);
        float4 a = xp[0], b = xp[1];
        xv[0] = a.x; xv[1] = a.y; xv[2] = a.z; xv[3] = a.w;
        xv[4] = b.x; xv[5] = b.y; xv[6] = b.z; xv[7] = b.w;
    }

    // ---- q = x@Wq + bq, weights via constant cache ----
    u64 A[4];
    #pragma unroll
    for (int j = 0; j < 4; j++) A[j] = cu(320 + j);
    #pragma unroll
    for (int k = 0; k < 8; k++) {
        u64 w0, w1_, w2_, w3_;
        cu2(k * 4 + 0, w0, w1_);
        cu2(k * 4 + 2, w2_, w3_);
        const u64 xk = bcast2(xv[k]);
        A[0] = fma2(xk, w0, A[0]);
        A[1] = fma2(xk, w1_, A[1]);
        A[2] = fma2(xk, w2_, A[2]);
        A[3] = fma2(xk, w3_, A[3]);
    }

    // ---- ca = cos(q + theta) ; <Z> via prefix/suffix products ----
    float z[8];
    {
        float ca[8];
        #pragma unroll
        for (int j = 0; j < 4; j++) {
            u64 s = add2(A[j], cu(328 + j));
            float a, b;
            up2(s, a, b); ca[2 * j] = __cosf(a); ca[2 * j + 1] = __cosf(b);
        }
        float s = ca[1] * ca[2]; s *= ca[3]; s *= ca[4]; s *= ca[5]; s *= ca[6]; s *= ca[7];
        z[0] = s;
        z[1] = ca[0] * ca[1];
        #pragma unroll
        for (int k = 2; k < 8; k++) z[k] = z[k - 1] * ca[k];
    }

    // ---- attn_out = z@Wc + bc ----
    #pragma unroll
    for (int j = 0; j < 4; j++) A[j] = cu(324 + j);
    #pragma unroll
    for (int k = 0; k < 8; k++) {
        u64 w0, w1_, w2_, w3_;
        cu2(32 + k * 4 + 0, w0, w1_);
        cu2(32 + k * 4 + 2, w2_, w3_);
        const u64 zk = bcast2(z[k]);
        A[0] = fma2(zk, w0, A[0]);
        A[1] = fma2(zk, w1_, A[1]);
        A[2] = fma2(zk, w2_, A[2]);
        A[3] = fma2(zk, w3_, A[3]);
    }

    // ---- residual + LN1 ----
    u64 x1p[4];
    {
        u64 r[4];
        #pragma unroll
        for (int j = 0; j < 4; j++)
            r[j] = add2(A[j], pack2(xv[2 * j], xv[2 * j + 1]));
        ln8c(r, 356, 360, x1p);
    }

    // ---- zf = cos(theta_ffn)*cos(x1)  (ctf prefolded in constant) ----
    float zf[8];
    #pragma unroll
    for (int j = 0; j < 4; j++) {
        float c0, c1, a, b;
        up2(cu(332 + j), c0, c1);
        up2(x1p[j], a, b);
        zf[2 * j]     = c0 * __cosf(a);
        zf[2 * j + 1] = c1 * __cosf(b);
    }

    // ---- fused FFN: 4 blocks of 4 hidden-pairs; weights via constant cache ----
    u64 f[8];
    #pragma unroll
    for (int j = 0; j < 8; j++) f[j] = 0ULL;
    #pragma unroll
    for (int b = 0; b < 4; b++) {
        u64 h[4];
        #pragma unroll
        for (int ip = 0; ip < 4; ip++) h[ip] = cu(336 + b * 4 + ip);
        #pragma unroll
        for (int j = 0; j < 8; j++) {
            u64 wa, wb, wc_, wd;
            cu2(64 + j * 16 + b * 4 + 0, wa, wb);
            cu2(64 + j * 16 + b * 4 + 2, wc_, wd);
            const u64 zb = bcast2(zf[j]);
            h[0] = fma2(zb, wa, h[0]);
            h[1] = fma2(zb, wb, h[1]);
            h[2] = fma2(zb, wc_, h[2]);
            h[3] = fma2(zb, wd, h[3]);
        }
        #pragma unroll
        for (int ip = 0; ip < 4; ip++) {
            const int p = b * 4 + ip;
            float a, c;
            up2(h[ip], a, c);
            const u64 hr = pack2(fmaxf(a, 0.f), fmaxf(c, 0.f));
            #pragma unroll
            for (int c2 = 0; c2 < 4; c2++) {
                u64 wa, wb;
                cu2(192 + p * 8 + 2 * c2, wa, wb);
                f[2 * c2]     = fma2(hr, wa, f[2 * c2]);
                f[2 * c2 + 1] = fma2(hr, wb, f[2 * c2 + 1]);
            }
        }
    }

    // ---- lane-fold + bias + residual ; LN2 ; store as 2x STG.128 ----
    u64 o[4];
    {
        float s[8];
        #pragma unroll
        for (int j = 0; j < 8; j++) {
            float a, b;
            up2(f[j], a, b); s[j] = a + b;
        }
        u64 r[4];
        #pragma unroll
        for (int j = 0; j < 4; j++)
            r[j] = add2(add2(pack2(s[2 * j], s[2 * j + 1]), cu(352 + j)), x1p[j]);
        ln8c(r, 364, 368, o);
    }
    {
        float4* op = reinterpret_cast<float4*>(out + (size_t)tok * NE);
        float a, b, c, d;
        up2(o[0], a, b); up2(o[1], c, d); op[0] = make_float4(a, b, c, d);
        up2(o[2], a, b); up2(o[3], c, d); op[1] = make_float4(a, b, c, d);
    }
}

extern "C" void kernel_launch(void* const* d_in, const int* in_sizes, int n_in,
                              void* d_out, int out_size)
{
    const float* x          = (const float*)d_in[0];
    const float* Wq         = (const float*)d_in[1];
    const float* bq         = (const float*)d_in[2];
    const float* theta_attn = (const float*)d_in[3];
    const float* Wc         = (const float*)d_in[4];
    const float* bc         = (const float*)d_in[5];
    const float* g1         = (const float*)d_in[6];
    const float* beta1      = (const float*)d_in[7];
    const float* theta_ffn  = (const float*)d_in[8];
    const float* W1         = (const float*)d_in[9];
    const float* b1         = (const float*)d_in[10];
    const float* W2         = (const float*)d_in[11];
    const float* b2         = (const float*)d_in[12];
    const float* g2         = (const float*)d_in[13];
    const float* beta2      = (const float*)d_in[14];

    // 1) gather + preprocess weights into staging (device global)
    pack_kernel<<<1, 256>>>(Wq, Wc, W1, W2, bq, bc, theta_attn, theta_ffn,
                            b1, b2, g1, beta1, g2, beta2);

    // 2) one D2D copy staging -> __constant__ (graph-capturable memcpy node)
    void* src = nullptr;
    cudaGetSymbolAddress(&src, d_stage);
    cudaMemcpyToSymbolAsync(cb, src, 744 * sizeof(float), 0,
                            cudaMemcpyDeviceToDevice, 0);

    // 3) main kernel: 1 token per thread
    const int tokens = out_size / NE;                     // 1,048,576
    const int blocks = (tokens + TPB - 1) / TPB;          // 4096
    tbq_kernel<<<blocks, TPB>>>(x, (float*)d_out, tokens);
}